// round 17
// baseline (speedup 1.0000x reference)
#include <cuda_runtime.h>
#include <cuda_bf16.h>
#include <cuda_fp16.h>
#include <math.h>
#include <stdint.h>

#define T_STEPS 512
#define BATCH   64
#define IN_DIM  1024
#define HID     1024
#define GATES   4096   // 4*HID, gate order i,g,f,o
#define NCTA    128

// ---------------- device scratch ----------------
__device__ float g_wx[(size_t)T_STEPS * BATCH * GATES];   // 512 MB
__device__ unsigned g_ctr;                                // step barrier counter
__device__ unsigned g_bar;                                // end-of-launch cleanup

__device__ __half g_xf[(size_t)T_STEPS * BATCH * IN_DIM]; // fp16 x
__device__ __half g_Wf[(size_t)GATES * IN_DIM];           // fp16 W transposed [N][K]
__device__ __half g_Rf[(size_t)GATES * HID];              // fp16 R transposed [N][K]
__device__ __half g_hf[2][BATCH * HID];                   // fp16 ping-pong h

// ---------------- helpers ----------------
__device__ __forceinline__ void mma16816h(float* c, const uint32_t* a, const uint32_t* b)
{
    asm volatile(
        "mma.sync.aligned.m16n8k16.row.col.f32.f16.f16.f32 "
        "{%0,%1,%2,%3}, {%4,%5,%6,%7}, {%8,%9}, {%0,%1,%2,%3};"
        : "+f"(c[0]), "+f"(c[1]), "+f"(c[2]), "+f"(c[3])
        : "r"(a[0]), "r"(a[1]), "r"(a[2]), "r"(a[3]), "r"(b[0]), "r"(b[1]));
}

__device__ __forceinline__ float tanh_fast(float x)
{
    float y;
    asm("tanh.approx.f32 %0, %1;" : "=f"(y) : "f"(x));
    return y;
}
__device__ __forceinline__ float sigmoid_fast(float x)
{
    return 0.5f * tanh_fast(0.5f * x) + 0.5f;
}

__device__ __forceinline__ float ldcg_f(const float* p)
{
    float v;
    asm volatile("ld.global.cg.f32 %0, [%1];" : "=f"(v) : "l"(p));
    return v;
}

// ---------------- conversion kernels ----------------
__global__ void convert_x(const float* __restrict__ x)
{
    size_t i = (size_t)blockIdx.x * blockDim.x + threadIdx.x;
    if (i < (size_t)T_STEPS * BATCH * IN_DIM)
        g_xf[i] = __float2half_rn(x[i]);
}

__global__ void convert_W(const float* __restrict__ src)
{
    __shared__ float tile[32][33];
    int n0 = blockIdx.x * 32, k0 = blockIdx.y * 32;
    int tx = threadIdx.x, ty = threadIdx.y;
#pragma unroll
    for (int i = 0; i < 32; i += 8)
        tile[ty + i][tx] = src[(size_t)(k0 + ty + i) * GATES + n0 + tx];
    __syncthreads();
#pragma unroll
    for (int i = 0; i < 32; i += 8)
        g_Wf[(size_t)(n0 + ty + i) * IN_DIM + k0 + tx] = __float2half_rn(tile[tx][ty + i]);
}

__global__ void convert_R(const float* __restrict__ src)
{
    __shared__ float tile[32][33];
    int n0 = blockIdx.x * 32, k0 = blockIdx.y * 32;
    int tx = threadIdx.x, ty = threadIdx.y;
#pragma unroll
    for (int i = 0; i < 32; i += 8)
        tile[ty + i][tx] = src[(size_t)(k0 + ty + i) * GATES + n0 + tx];
    __syncthreads();
#pragma unroll
    for (int i = 0; i < 32; i += 8)
        g_Rf[(size_t)(n0 + ty + i) * HID + k0 + tx] = __float2half_rn(tile[tx][ty + i]);
}

// ---------------- wx GEMM: fp16, K-chunk 64, cp.async double-buffered ---------
#define WXS 72                          // smem k-stride (64 + 8 pad)
#define WXC (128 * WXS)                 // elems per array per buffer
#define WX_SMEM (2 * 2 * WXC * 2)       // 2 bufs x (A,B) x fp16 = 73728 B

__device__ __forceinline__ void wx_stage(uint32_t smb, size_t m0, int n0,
                                         int k0, int b, int tid)
{
#pragma unroll
    for (int arr = 0; arr < 2; arr++) {
        const __half* sp = arr ? g_Wf : g_xf;
        size_t base = arr ? (size_t)n0 : m0;
#pragma unroll
        for (int rep = 0; rep < 4; rep++) {
            int id = tid + rep * 256;             // 0..1023
            int row = id >> 3, seg = id & 7;      // 128 rows x 8 x 16B
            const __half* src = sp + (base + row) * IN_DIM + k0 + seg * 8;
            uint32_t dst = smb + (uint32_t)(((b * 2 + arr) * WXC
                                             + row * WXS + seg * 8) * 2);
            asm volatile("cp.async.cg.shared.global [%0], [%1], 16;"
                         :: "r"(dst), "l"(src));
        }
    }
    asm volatile("cp.async.commit_group;");
}

__global__ __launch_bounds__(256) void wx_mma(const float* __restrict__ bias)
{
    extern __shared__ __align__(16) unsigned char wxsm[];
    __half* S = (__half*)wxsm;
    uint32_t smb = (uint32_t)__cvta_generic_to_shared(S);

    int tid  = threadIdx.x;
    int lane = tid & 31, w = tid >> 5;
    int g = lane >> 2, tq = lane & 3;
    size_t m0 = (size_t)blockIdx.y * 128;
    int n0 = blockIdx.x * 128;
    int wm = w & 1, wn = w >> 1;

    float acc[4][4][4];
#pragma unroll
    for (int mt = 0; mt < 4; mt++)
#pragma unroll
        for (int nt = 0; nt < 4; nt++)
#pragma unroll
            for (int r = 0; r < 4; r++) acc[mt][nt][r] = 0.f;

    wx_stage(smb, m0, n0, 0, 0, tid);

    for (int kc = 0; kc < 16; kc++) {
        int cur = kc & 1;
        if (kc < 15) {
            wx_stage(smb, m0, n0, (kc + 1) * 64, cur ^ 1, tid);
            asm volatile("cp.async.wait_group 1;");
        } else {
            asm volatile("cp.async.wait_group 0;");
        }
        __syncthreads();

        const __half* A = S + (cur * 2 + 0) * WXC;
        const __half* B = S + (cur * 2 + 1) * WXC;

#pragma unroll
        for (int ks = 0; ks < 4; ks++) {
            int ko = ks * 16;
            uint32_t bf[4][2];
#pragma unroll
            for (int nt = 0; nt < 4; nt++) {
                int r = wn * 32 + nt * 8 + g;
                bf[nt][0] = *(const uint32_t*)&B[r * WXS + ko + 2 * tq];
                bf[nt][1] = *(const uint32_t*)&B[r * WXS + ko + 2 * tq + 8];
            }
#pragma unroll
            for (int mt = 0; mt < 4; mt++) {
                int r0 = wm * 64 + mt * 16 + g, r1 = r0 + 8;
                uint32_t af[4];
                af[0] = *(const uint32_t*)&A[r0 * WXS + ko + 2 * tq];
                af[1] = *(const uint32_t*)&A[r1 * WXS + ko + 2 * tq];
                af[2] = *(const uint32_t*)&A[r0 * WXS + ko + 2 * tq + 8];
                af[3] = *(const uint32_t*)&A[r1 * WXS + ko + 2 * tq + 8];
#pragma unroll
                for (int nt = 0; nt < 4; nt++) mma16816h(acc[mt][nt], af, bf[nt]);
            }
        }
        __syncthreads();
    }

#pragma unroll
    for (int mt = 0; mt < 4; mt++) {
        size_t row = m0 + wm * 64 + mt * 16 + g;
#pragma unroll
        for (int nt = 0; nt < 4; nt++) {
            int col = n0 + wn * 32 + nt * 8 + 2 * tq;
            g_wx[row * GATES + col]           = acc[mt][nt][0] + bias[col];
            g_wx[row * GATES + col + 1]       = acc[mt][nt][1] + bias[col + 1];
            g_wx[(row + 8) * GATES + col]     = acc[mt][nt][2] + bias[col];
            g_wx[(row + 8) * GATES + col + 1] = acc[mt][nt][3] + bias[col + 1];
        }
    }
}

// ---------------- persistent LSTM recurrence v10 ----------------
// R16 skeleton (512 thr, 4-way k-split, counter barrier) with single-shot
// h staging: each warp stages its whole 8 KB slice (16 rows x 256 k) in ONE
// cp.async burst -> one wait -> 64 uninterrupted mma. Reduction scratch is
// OVERLAID on the h region (h reads complete before reduction store; next
// step's staging happens after the barrier).
#define RSTR 1032                                  // fp16 elems per R row
#define HSTR2 264                                  // h k-stride (256 + 8 pad)
#define HBUF_B (16 * HSTR2 * 2)                    // 8448 B per warp
#define H_REGION (16 * HBUF_B)                     // 135168 B
#define SMEM_PERS (32 * RSTR * 2 + H_REGION)       // 66048 + 135168 = 201216 B

__device__ __forceinline__ void stage_all(uint32_t hbase_sm, const __half* hsrc,
                                          int w, int grp, int wm, int lane)
{
#pragma unroll
    for (int s = 0; s < 16; s++) {                 // row s: 512B contiguous
        const __half* src = hsrc + (size_t)(wm * 16 + s) * HID + grp * 256 + lane * 8;
        uint32_t dst = hbase_sm
            + (uint32_t)(w * HBUF_B + s * (HSTR2 * 2) + lane * 16);
        asm volatile("cp.async.cg.shared.global [%0], [%1], 16;" :: "r"(dst), "l"(src));
    }
    asm volatile("cp.async.commit_group;");
}

__global__ __launch_bounds__(512) void lstm_persistent(float* __restrict__ out_base)
{
    extern __shared__ __align__(16) unsigned char smem_raw[];
    __half* Rf = (__half*)smem_raw;
    __half* Hbase = Rf + 32 * RSTR;
    float* Red = (float*)Hbase;                    // OVERLAY on h region
    uint32_t hbase_sm = (uint32_t)__cvta_generic_to_shared(Hbase);

    const int tid  = threadIdx.x;
    const int lane = tid & 31, w = tid >> 5;
    const int g = lane >> 2, tq = lane & 3;
    const int grp = w >> 2, wm = w & 3;
    const int hc0 = blockIdx.x * 8;

    for (int rep = 0; rep < 8; rep++) {
        int id = rep * 512 + tid;
        int row = id >> 7, seg = id & 127;
        size_t src = (size_t)((row >> 3) * HID + hc0 + (row & 7)) * HID + seg * 8;
        *(uint4*)&Rf[row * RSTR + seg * 8] = *(const uint4*)&g_Rf[src];
    }
    __syncthreads();

    const int jj = grp >> 1, cm = grp & 1;
    const int brow = wm * 16 + g + jj * 8;
    const int col  = hc0 + 2 * tq + cm;
    const int oidx = brow * HID + col;
    float c_reg = 0.f;

    for (int t = 0; t < T_STEPS; t++) {
        // stage this warp's FULL h slice first (max MLP), then prefetch wx
        if (t > 0)
            stage_all(hbase_sm, g_hf[(t - 1) & 1], w, grp, wm, lane);

        float wxp[4];
        {
            const float* wb = g_wx + (size_t)t * BATCH * GATES + (size_t)brow * GATES;
#pragma unroll
            for (int gate = 0; gate < 4; gate++)
                wxp[gate] = ldcg_f(wb + gate * HID + col);
        }

        float acc[4][4];
#pragma unroll
        for (int nt = 0; nt < 4; nt++)
#pragma unroll
            for (int r = 0; r < 4; r++) acc[nt][r] = 0.f;

        if (t > 0) {
            asm volatile("cp.async.wait_group 0;");
            __syncwarp();

            const __half* HC = (const __half*)
                ((const unsigned char*)Hbase + w * HBUF_B);
#pragma unroll
            for (int kt = 0; kt < 16; kt++) {
                int ko = kt * 16 + 2 * tq;
                uint32_t ah[4];
                ah[0] = *(const uint32_t*)&HC[g * HSTR2 + ko];
                ah[1] = *(const uint32_t*)&HC[(g + 8) * HSTR2 + ko];
                ah[2] = *(const uint32_t*)&HC[g * HSTR2 + ko + 8];
                ah[3] = *(const uint32_t*)&HC[(g + 8) * HSTR2 + ko + 8];
                int kR = grp * 256 + kt * 16 + 2 * tq;
                uint32_t bf[4][2];
#pragma unroll
                for (int nt = 0; nt < 4; nt++) {
                    int rr = nt * 8 + g;
                    bf[nt][0] = *(const uint32_t*)&Rf[rr * RSTR + kR];
                    bf[nt][1] = *(const uint32_t*)&Rf[rr * RSTR + kR + 8];
                }
#pragma unroll
                for (int nt = 0; nt < 4; nt++) mma16816h(acc[nt], ah, bf[nt]);
            }
        }

        // all h reads done before Red overlays the h region
        __syncthreads();

        // 4-way cross-group reduction: publish the 3 j-slots others need
        {
            float* slot = Red + (size_t)(w * 32 + lane) * 17;
#pragma unroll
            for (int nt = 0; nt < 4; nt++)
#pragma unroll
                for (int j = 0; j < 4; j++)
                    if (j != grp) slot[nt * 4 + j] = acc[nt][j];
        }
        __syncthreads();

        float h, cn;
        {
            float v[4];
#pragma unroll
            for (int nt = 0; nt < 4; nt++) v[nt] = acc[nt][grp];
#pragma unroll
            for (int c = 0; c < 4; c++) {
                if (c == grp) continue;
                const float* slot = Red + (size_t)(((c * 4 + wm) * 32 + lane)) * 17;
#pragma unroll
                for (int nt = 0; nt < 4; nt++) v[nt] += slot[nt * 4 + grp];
            }

            float ii = sigmoid_fast(v[0] + wxp[0]);
            float gg = tanh_fast(v[1] + wxp[1]);
            float ff = sigmoid_fast(v[2] + wxp[2]);
            float oo = sigmoid_fast(v[3] + wxp[3]);
            cn = ff * c_reg + ii * gg;
            c_reg = cn;
            h = oo * tanh_fast(cn);
            g_hf[t & 1][oidx] = __float2half_rn(h);   // the only cross-CTA store
        }

        // publish + detect (grid release/acquire via one counter)
        if (t < T_STEPS - 1) {
            __syncthreads();                    // CTA-scope release of g_hf stores
            if (tid == 0) {
                asm volatile("red.release.gpu.global.add.u32 [%0], 1;"
                             :: "l"(&g_ctr) : "memory");
                unsigned target = (unsigned)NCTA * (unsigned)(t + 1);
                unsigned v;
                do {
                    asm volatile("ld.acquire.gpu.global.u32 %0, [%1];"
                                 : "=r"(v) : "l"(&g_ctr) : "memory");
                } while (v < target);
            }
            __syncthreads();                    // distribute acquire
        }

        // deferred fp32 output store — off the publish critical path
        out_base[(size_t)t * BATCH * HID + oidx] = h;
        if (t == T_STEPS - 1) {
            size_t base = (size_t)T_STEPS * BATCH * HID;
            out_base[base + oidx] = h;
            out_base[base + BATCH * HID + oidx] = cn;
        }
    }

    // cleanup for graph replay (after ALL CTAs complete)
    if (tid == 0) {
        __threadfence();
        atomicAdd(&g_bar, 1u);
        if (blockIdx.x == 0) {
            while (atomicAdd(&g_bar, 0u) < NCTA) __nanosleep(100);
            g_ctr = 0;
            __threadfence();
            g_bar = 0;
        }
    }
}

extern "C" void kernel_launch(void* const* d_in, const int* in_sizes, int n_in,
                              void* d_out, int out_size)
{
    const float* x    = (const float*)d_in[0];
    const float* Wk   = (const float*)d_in[1];
    const float* Rk   = (const float*)d_in[2];
    const float* bias = (const float*)d_in[3];
    float* out = (float*)d_out;

    cudaFuncSetAttribute(lstm_persistent,
                         cudaFuncAttributeMaxDynamicSharedMemorySize, SMEM_PERS);
    cudaFuncSetAttribute(wx_mma,
                         cudaFuncAttributeMaxDynamicSharedMemorySize, WX_SMEM);

    size_t nx = (size_t)T_STEPS * BATCH * IN_DIM;
    convert_x<<<(unsigned)((nx + 255) / 256), 256>>>(x);
    convert_W<<<dim3(GATES / 32, IN_DIM / 32), dim3(32, 8)>>>(Wk);
    convert_R<<<dim3(GATES / 32, HID / 32), dim3(32, 8)>>>(Rk);

    wx_mma<<<dim3(GATES / 128, (T_STEPS * BATCH) / 128), 256, WX_SMEM>>>(bias);

    lstm_persistent<<<NCTA, 512, SMEM_PERS>>>(out);
}